// round 3
// baseline (speedup 1.0000x reference)
#include <cuda_runtime.h>
#include <cstdint>

// UpsampleNearest4D: x (2,8,8,16,64,64) f32, x2 on axes 2..5.
// Output (2,8,16,32,128,128) = 134,217,728 floats = 33,554,432 float4.
//
// OUTPUT-DRIVEN, fully linear write stream: thread i writes output float4 i.
// Block b writes 4KB contiguous; consecutive blocks adjacent -> one linear
// 512MB DRAM write sweep (max row-buffer locality, no scattered evictions).
//
// Read side: out float4 column ox4 (out x = 4*ox4..4*ox4+3) maps to input
// float2 column ox4 (in x = 2*ox4..2*ox4+1). Input is 32 MiB -> L2-resident;
// y-duplicate rows are adjacent warps (L1 hit), t/z duplicates hit L2.
//
// Input  (f2 units): NC=16, T=8,  Z=16, Y=64,  row = 32 f2
// Output (f4 units): NC=16, OT=16, OZ=32, OY=128, row = 32 f4

__global__ __launch_bounds__(256) void upsample4d_out_kernel(
    const float2* __restrict__ in, float4* __restrict__ out)
{
    unsigned o = blockIdx.x * 256u + threadIdx.x;    // [0, 33554432)

    unsigned ox4 = o & 31u;             // = input float2 column
    unsigned r   = o >> 5;
    unsigned oy  = r & 127u; r >>= 7;
    unsigned oz  = r & 31u;  r >>= 5;
    unsigned ot  = r & 15u;  r >>= 4;
    unsigned nc  = r;                   // [0,16)

    unsigned iy = oy >> 1, iz = oz >> 1, it = ot >> 1;
    unsigned iidx = ((((nc * 8u + it) * 16u + iz) * 64u + iy) * 32u) + ox4;

    float2 v = __ldg(&in[iidx]);
    float4 w = make_float4(v.x, v.x, v.y, v.y);

    // Streaming store: output is write-once, evict-first in L2.
    asm volatile(
        "st.global.cs.v4.f32 [%0], {%1,%2,%3,%4};"
        :: "l"(&out[o]), "f"(w.x), "f"(w.y), "f"(w.z), "f"(w.w)
        : "memory");
}

extern "C" void kernel_launch(void* const* d_in, const int* in_sizes, int n_in,
                              void* d_out, int out_size)
{
    const float2* in = (const float2*)d_in[0];
    float4* out = (float4*)d_out;

    const unsigned n_threads = 33554432u;   // output float4 count
    upsample4d_out_kernel<<<n_threads / 256u, 256u>>>(in, out);
}

// round 5
// speedup vs baseline: 1.1804x; 1.1804x over previous
#include <cuda_runtime.h>
#include <cstdint>

// UpsampleNearest4D: x (2,8,8,16,64,64) f32, x2 on axes 2..5.
// Output (2,8,16,32,128,128).
//
// Input-driven (best structure, R1): one thread per input float2.
// Each thread writes 8 float4 {a,a,b,b} stores covering the 2x2x2x2
// (t,z,y,x) duplication; each warp-store = 512B contiguous, every
// output 128B line fully written by one instruction (no RFO).
//
// R4 delta vs R1: st.global.cs (evict-first) on the write stream so L2
// schedules writeback eagerly instead of waiting for set-conflict
// evictions; 512-thread blocks.

__global__ __launch_bounds__(512) void upsample4d_kernel(
    const float2* __restrict__ in, float4* __restrict__ out)
{
    unsigned idx = blockIdx.x * 512u + threadIdx.x;   // [0, 4194304)

    unsigned x2 = idx & 31u;            // float2 column within input row
    unsigned r  = idx >> 5;
    unsigned y  = r & 63u;  r >>= 6;
    unsigned z  = r & 15u;  r >>= 4;
    unsigned t  = r & 7u;   r >>= 3;
    unsigned nc = r;                    // [0,16)

    float2 v = __ldg(&in[idx]);
    float4 o = make_float4(v.x, v.x, v.y, v.y);

    // Output strides in float4 units: row = 128/4 = 32
    const unsigned SY = 32u;                 // one output row (512B)
    const unsigned SZ = 128u * 32u;          // OY rows
    const unsigned ST = 32u * 128u * 32u;    // OZ * OY rows

    unsigned base = ((((nc * 16u + 2u * t) * 32u + 2u * z) * 128u + 2u * y) * 32u) + x2;

    float4* p0 = out + base;
    float4* p1 = out + base + ST;

    #define STCS(ptr) asm volatile( \
        "st.global.cs.v4.f32 [%0], {%1,%2,%3,%4};" \
        :: "l"(ptr), "f"(o.x), "f"(o.y), "f"(o.z), "f"(o.w) : "memory")

    STCS(p0);
    STCS(p0 + SY);
    STCS(p0 + SZ);
    STCS(p0 + SZ + SY);
    STCS(p1);
    STCS(p1 + SY);
    STCS(p1 + SZ);
    STCS(p1 + SZ + SY);

    #undef STCS
}

extern "C" void kernel_launch(void* const* d_in, const int* in_sizes, int n_in,
                              void* d_out, int out_size)
{
    const float2* in = (const float2*)d_in[0];
    float4* out = (float4*)d_out;

    // 8,388,608 input floats -> 4,194,304 float2 threads
    const unsigned n_threads = 8u * 1024u * 1024u / 2u;
    upsample4d_kernel<<<n_threads / 512u, 512u>>>(in, out);
}